// round 13
// baseline (speedup 1.0000x reference)
#include <cuda_runtime.h>
#include <cuda_fp16.h>

#define NN 100000
#define EE 1600000
#define HH 4
#define CC 32
#define DIM 128
#define NEG_SLOPE 0.2f
#define BN_EPS 1e-5f

// ---------------- scratch (static device globals; no allocs allowed) -------
__device__ __half2 g_h2[(size_t)NN * (DIM / 2)];  // x @ W in fp16 (25.6 MB)
__device__ float   g_acc[(size_t)NN * DIM];       // normalized+biased v (51.2 MB)
__device__ float   g_asrc[NN * HH];
__device__ float   g_adst[NN * HH];
__device__ int     g_deg[NN];
__device__ int     g_off[NN];
__device__ int     g_cur[NN];
__device__ int     g_total;
__device__ int     g_srcs[EE];                    // CSR src ids (6.4 MB)
__device__ float   g_colsum[DIM];
__device__ float   g_colsq[DIM];

// ---------------- 0. zero small scratch ------------------------------------
__global__ void zero_kernel() {
    int i = blockIdx.x * blockDim.x + threadIdx.x;
    if (i < NN) g_deg[i] = 0;
    if (i == 0) g_total = 0;
    if (i < DIM) { g_colsum[i] = 0.f; g_colsq[i] = 0.f; }
}

// ---------------- CSR build: histogram, offsets, scatter --------------------
__global__ void hist_kernel(const int* __restrict__ ei) {
    int e = blockIdx.x * blockDim.x + threadIdx.x;
    if (e < EE) atomicAdd(&g_deg[__ldg(&ei[EE + e])], 1);
}

// warp-aggregated slot allocation: buckets are disjoint but NOT ordered by
// node id — agg only needs disjointness.
__global__ void offsets_kernel() {
    int i = blockIdx.x * blockDim.x + threadIdx.x;
    int lane = threadIdx.x & 31;
    int v = (i < NN) ? g_deg[i] : 0;
    int x = v;
#pragma unroll
    for (int d = 1; d < 32; d <<= 1) {
        int y = __shfl_up_sync(0xffffffffu, x, d);
        if (lane >= d) x += y;
    }
    int total = __shfl_sync(0xffffffffu, x, 31);
    int base = 0;
    if (lane == 31 && total > 0) base = atomicAdd(&g_total, total);
    base = __shfl_sync(0xffffffffu, base, 31);
    if (i < NN) {
        int o = base + x - v;
        g_off[i] = o;
        g_cur[i] = o;
    }
}

__global__ void scatter_kernel(const int* __restrict__ ei) {
    int e = blockIdx.x * blockDim.x + threadIdx.x;
    if (e < EE) {
        int s = __ldg(&ei[e]);
        int d = __ldg(&ei[EE + e]);
        int idx = atomicAdd(&g_cur[d], 1);
        g_srcs[idx] = s;
    }
}

// ---------------- 1. h = x @ W via tf32 mma (tensor pipe) ------------------
#define GM 128                       // nodes per block
#define XSTR 132
#define WSTR 136

__device__ __forceinline__ unsigned f2tf32(float f) {
    unsigned u;
    asm("cvt.rna.tf32.f32 %0, %1;" : "=r"(u) : "f"(f));
    return u;
}
__device__ __forceinline__ float pick4(float a, float b, float c, float d, int t) {
    return t == 0 ? a : (t == 1 ? b : (t == 2 ? c : d));
}

__global__ void gemm_kernel(const float* __restrict__ x,
                            const float* __restrict__ W,
                            const float* __restrict__ att_s,
                            const float* __restrict__ att_d) {
    extern __shared__ unsigned smu[];
    unsigned* ws = smu;                   // 128 * 136 words
    unsigned* xs = smu + DIM * WSTR;      // 128 * 132 words
    const int tid = threadIdx.x;
    const int nb  = blockIdx.x * GM;

    for (int i = tid * 4; i < DIM * DIM; i += 256 * 4) {
        int k = i >> 7, n = i & 127;
        float4 w = *(const float4*)&W[i];
        uint4 u = make_uint4(f2tf32(w.x), f2tf32(w.y), f2tf32(w.z), f2tf32(w.w));
        *(uint4*)&ws[k * WSTR + n] = u;
    }
    for (int i = tid * 4; i < GM * DIM; i += 256 * 4) {
        int r = i >> 7, c = i & 127;
        uint4 u = make_uint4(0u, 0u, 0u, 0u);
        if (nb + r < NN) {
            float4 v = *(const float4*)&x[(size_t)(nb + r) * DIM + c];
            u = make_uint4(f2tf32(v.x), f2tf32(v.y), f2tf32(v.z), f2tf32(v.w));
        }
        *(uint4*)&xs[r * XSTR + c] = u;
    }
    __syncthreads();

    const int warp = tid >> 5, lane = tid & 31;
    const int g = lane >> 2, t = lane & 3;
    const unsigned* xw = xs + (warp * 16) * XSTR;

    float d[16][4];
#pragma unroll
    for (int nt = 0; nt < 16; nt++)
#pragma unroll
        for (int j = 0; j < 4; j++) d[nt][j] = 0.f;

#pragma unroll
    for (int ks = 0; ks < 16; ks++) {
        const int k0 = ks * 8;
        unsigned a0 = xw[g * XSTR + k0 + t];
        unsigned a1 = xw[(g + 8) * XSTR + k0 + t];
        unsigned a2 = xw[g * XSTR + k0 + t + 4];
        unsigned a3 = xw[(g + 8) * XSTR + k0 + t + 4];
#pragma unroll
        for (int nt = 0; nt < 16; nt++) {
            unsigned b0 = ws[(k0 + t) * WSTR + nt * 8 + g];
            unsigned b1 = ws[(k0 + t + 4) * WSTR + nt * 8 + g];
            asm volatile(
                "mma.sync.aligned.m16n8k8.row.col.f32.tf32.tf32.f32 "
                "{%0,%1,%2,%3}, {%4,%5,%6,%7}, {%8,%9}, {%0,%1,%2,%3};"
                : "+f"(d[nt][0]), "+f"(d[nt][1]), "+f"(d[nt][2]), "+f"(d[nt][3])
                : "r"(a0), "r"(a1), "r"(a2), "r"(a3), "r"(b0), "r"(b1));
        }
    }

    const int node0 = nb + warp * 16;
    const int row0 = node0 + g, row1 = node0 + g + 8;

    float ps[2][4], pd[2][4];
#pragma unroll
    for (int r = 0; r < 2; r++)
#pragma unroll
        for (int h = 0; h < 4; h++) { ps[r][h] = 0.f; pd[r][h] = 0.f; }

#pragma unroll
    for (int nt = 0; nt < 16; nt++) {
        const int head = nt >> 2;
        const int cc = ((nt & 3) * 8) + 2 * t;
        float2 as = *(const float2*)&att_s[head * CC + cc];
        float2 ad = *(const float2*)&att_d[head * CC + cc];
        ps[0][head] += d[nt][0] * as.x + d[nt][1] * as.y;
        ps[1][head] += d[nt][2] * as.x + d[nt][3] * as.y;
        pd[0][head] += d[nt][0] * ad.x + d[nt][1] * ad.y;
        pd[1][head] += d[nt][2] * ad.x + d[nt][3] * ad.y;
    }
#pragma unroll
    for (int r = 0; r < 2; r++)
#pragma unroll
        for (int h = 0; h < 4; h++) {
            ps[r][h] += __shfl_xor_sync(0xffffffffu, ps[r][h], 1);
            ps[r][h] += __shfl_xor_sync(0xffffffffu, ps[r][h], 2);
            pd[r][h] += __shfl_xor_sync(0xffffffffu, pd[r][h], 1);
            pd[r][h] += __shfl_xor_sync(0xffffffffu, pd[r][h], 2);
        }
    if (row0 < NN) {
        g_asrc[row0 * HH + t] = pick4(ps[0][0], ps[0][1], ps[0][2], ps[0][3], t);
        g_adst[row0 * HH + t] = pick4(pd[0][0], pd[0][1], pd[0][2], pd[0][3], t);
    }
    if (row1 < NN) {
        g_asrc[row1 * HH + t] = pick4(ps[1][0], ps[1][1], ps[1][2], ps[1][3], t);
        g_adst[row1 * HH + t] = pick4(pd[1][0], pd[1][1], pd[1][2], pd[1][3], t);
    }

#pragma unroll
    for (int nt = 0; nt < 16; nt++) {
        if (row0 < NN)
            g_h2[(size_t)row0 * (DIM / 2) + nt * 4 + t] =
                __floats2half2_rn(d[nt][0], d[nt][1]);
        if (row1 < NN)
            g_h2[(size_t)row1 * (DIM / 2) + nt * 4 + t] =
                __floats2half2_rn(d[nt][2], d[nt][3]);
    }
}

// ---------------- 2. gather-aggregate, one warp per dst (no atomics) -------
// Two-stage software pipeline: next dst's metadata AND its first 32 src ids
// are prefetched during the current dst's gather/accumulate phase, removing
// both L2 hops (off -> srcs) from the per-dst critical path.
#define AG_WARPS 8
#define AG_GRID  592
#define AG_STEP  (AG_GRID * AG_WARPS)
__global__ void agg_kernel(const float* __restrict__ bias) {
    __shared__ float4 s_sum[AG_WARPS * 32];
    __shared__ float4 s_sq [AG_WARPS * 32];
    const int warp = threadIdx.x >> 5, lane = threadIdx.x & 31;
    const int ph = lane & 3;           // head this lane's logit belongs to
    const int pe = lane >> 2;          // edge slot (0..7) this lane scores
    const int myh = lane >> 3;         // head of this lane's 4 columns
    const float4 bv = *(const float4*)&bias[lane * 4];

    float4 csum = make_float4(0.f, 0.f, 0.f, 0.f);
    float4 csq  = make_float4(0.f, 0.f, 0.f, 0.f);

    int dst = blockIdx.x * AG_WARPS + warp;
    // prologue prefetch for first dst
    int deg = 0, off = 0, sv_pre = 0;
    float adp = 0.f, asp = 0.f;
    uint2 rs = make_uint2(0u, 0u);
    if (dst < NN) {
        deg = g_deg[dst]; off = g_off[dst];
        adp = __ldg(&g_adst[dst * HH + ph]);
        asp = __ldg(&g_asrc[dst * HH + ph]);
        rs  = *(const uint2*)&g_h2[(size_t)dst * (DIM / 2) + lane * 2];
        if (lane < min(deg, 32)) sv_pre = __ldg(&g_srcs[off + lane]);
    }

    while (dst < NN) {
        // ---- prefetch next dst: metadata + first src-id chunk --------------
        const int nd = dst + AG_STEP;
        int ndeg = 0, noff = 0, nsv = 0;
        float nadp = 0.f, nasp = 0.f;
        uint2 nrs = make_uint2(0u, 0u);
        if (nd < NN) {
            ndeg = g_deg[nd]; noff = g_off[nd];
            nadp = __ldg(&g_adst[nd * HH + ph]);
            nasp = __ldg(&g_asrc[nd * HH + ph]);
            nrs  = *(const uint2*)&g_h2[(size_t)nd * (DIM / 2) + lane * 2];
        }
        if (lane < min(ndeg, 32)) nsv = __ldg(&g_srcs[noff + lane]);

        // ---- process current dst -------------------------------------------
        float l0 = asp + adp;
        l0 = l0 > 0.f ? l0 : NEG_SLOPE * l0;
        float p_self = __expf(l0);
        float s_part = (lane < 4) ? p_self : 0.f;

        float pw0 = __shfl_sync(0xffffffffu, p_self, myh);
        float2 a0 = __half22float2(*(__half2*)&rs.x);
        float2 a1 = __half22float2(*(__half2*)&rs.y);
        float4 acc = make_float4(a0.x * pw0, a0.y * pw0, a1.x * pw0, a1.y * pw0);

        for (int c = 0; c < deg; c += 32) {
            const int nc = min(32, deg - c);
            int sv;
            if (c == 0) sv = sv_pre;
            else {
                sv = 0;
                if (lane < nc) sv = __ldg(&g_srcs[off + c + lane]);
            }

#pragma unroll
            for (int h = 0; h < 2; h++) {
                const int e0 = h * 16;
                const int nv = nc - e0;               // valid edges this half
                if (nv <= 0) break;

                float pA = 0.f, pB = 0.f;
                int sA = __shfl_sync(0xffffffffu, sv, e0 + pe);
                int sB = __shfl_sync(0xffffffffu, sv, e0 + pe + 8);
                if (pe < nv) {
                    float ll = __ldg(&g_asrc[sA * HH + ph]) + adp;
                    ll = ll > 0.f ? ll : NEG_SLOPE * ll;
                    pA = __expf(ll);
                }
                if (pe + 8 < nv) {
                    float ll = __ldg(&g_asrc[sB * HH + ph]) + adp;
                    ll = ll > 0.f ? ll : NEG_SLOPE * ll;
                    pB = __expf(ll);
                }
                s_part += pA + pB;

                uint2 raw[16];
#pragma unroll
                for (int e = 0; e < 16; e++) {
                    if (e < nv) {                     // warp-uniform
                        int se = __shfl_sync(0xffffffffu, sv, e0 + e);
                        raw[e] = *(const uint2*)&g_h2[(size_t)se * (DIM / 2) + lane * 2];
                    }
                }
#pragma unroll
                for (int e = 0; e < 16; e++) {
                    if (e < nv) {
                        float pw = (e < 8)
                            ? __shfl_sync(0xffffffffu, pA, e * 4 + myh)
                            : __shfl_sync(0xffffffffu, pB, (e - 8) * 4 + myh);
                        float2 f0 = __half22float2(*(__half2*)&raw[e].x);
                        float2 f1 = __half22float2(*(__half2*)&raw[e].y);
                        acc.x = fmaf(f0.x, pw, acc.x);
                        acc.y = fmaf(f0.y, pw, acc.y);
                        acc.z = fmaf(f1.x, pw, acc.z);
                        acc.w = fmaf(f1.y, pw, acc.w);
                    }
                }
            }
        }

        float st = s_part;
        st += __shfl_xor_sync(0xffffffffu, st, 4);
        st += __shfl_xor_sync(0xffffffffu, st, 8);
        st += __shfl_xor_sync(0xffffffffu, st, 16);
        float r = 1.f / (__shfl_sync(0xffffffffu, st, myh) + 1e-16f);

        float4 v;
        v.x = fmaf(acc.x, r, bv.x);
        v.y = fmaf(acc.y, r, bv.y);
        v.z = fmaf(acc.z, r, bv.z);
        v.w = fmaf(acc.w, r, bv.w);
        *(float4*)&g_acc[(size_t)dst * DIM + lane * 4] = v;

        csum.x += v.x; csum.y += v.y; csum.z += v.z; csum.w += v.w;
        csq.x = fmaf(v.x, v.x, csq.x); csq.y = fmaf(v.y, v.y, csq.y);
        csq.z = fmaf(v.z, v.z, csq.z); csq.w = fmaf(v.w, v.w, csq.w);

        // ---- rotate pipeline ----
        dst = nd; deg = ndeg; off = noff; adp = nadp; asp = nasp;
        rs = nrs; sv_pre = nsv;
    }

    s_sum[warp * 32 + lane] = csum;
    s_sq [warp * 32 + lane] = csq;
    __syncthreads();
    if (warp == 0) {
#pragma unroll
        for (int w = 1; w < AG_WARPS; w++) {
            float4 a = s_sum[w * 32 + lane], b = s_sq[w * 32 + lane];
            csum.x += a.x; csum.y += a.y; csum.z += a.z; csum.w += a.w;
            csq.x  += b.x; csq.y  += b.y; csq.z  += b.z; csq.w  += b.w;
        }
        atomicAdd(&g_colsum[lane * 4 + 0], csum.x);
        atomicAdd(&g_colsum[lane * 4 + 1], csum.y);
        atomicAdd(&g_colsum[lane * 4 + 2], csum.z);
        atomicAdd(&g_colsum[lane * 4 + 3], csum.w);
        atomicAdd(&g_colsq[lane * 4 + 0], csq.x);
        atomicAdd(&g_colsq[lane * 4 + 1], csq.y);
        atomicAdd(&g_colsq[lane * 4 + 2], csq.z);
        atomicAdd(&g_colsq[lane * 4 + 3], csq.w);
    }
}

// ---------------- 3. BN fold + apply + residual + ReLU ---------------------
__global__ void final_kernel(const float* __restrict__ x,
                             const float* __restrict__ gamma,
                             const float* __restrict__ beta,
                             float* __restrict__ out) {
    int i = blockIdx.x * blockDim.x + threadIdx.x;   // float4 index
    if (i >= NN * DIM / 4) return;
    int cb = (i & 31) * 4;
    float4 cs = *(const float4*)&g_colsum[cb];
    float4 cq = *(const float4*)&g_colsq[cb];
    float4 gm = *(const float4*)&gamma[cb];
    float4 bt = *(const float4*)&beta[cb];
    const float invn = 1.f / NN;
    float mx = cs.x * invn, my = cs.y * invn, mz = cs.z * invn, mw = cs.w * invn;
    float scx = gm.x * rsqrtf(cq.x * invn - mx * mx + BN_EPS);
    float scy = gm.y * rsqrtf(cq.y * invn - my * my + BN_EPS);
    float scz = gm.z * rsqrtf(cq.z * invn - mz * mz + BN_EPS);
    float scw = gm.w * rsqrtf(cq.w * invn - mw * mw + BN_EPS);
    float shx = bt.x - mx * scx, shy = bt.y - my * scy;
    float shz = bt.z - mz * scz, shw = bt.w - mw * scw;

    float4 v  = ((const float4*)g_acc)[i];
    float4 xv = ((const float4*)x)[i];
    float4 o;
    o.x = fmaxf(fmaf(scx, v.x, shx) + xv.x, 0.f);
    o.y = fmaxf(fmaf(scy, v.y, shy) + xv.y, 0.f);
    o.z = fmaxf(fmaf(scz, v.z, shz) + xv.z, 0.f);
    o.w = fmaxf(fmaf(scw, v.w, shw) + xv.w, 0.f);
    ((float4*)out)[i] = o;
}

// ---------------- launch ----------------------------------------------------
extern "C" void kernel_launch(void* const* d_in, const int* in_sizes, int n_in,
                              void* d_out, int out_size) {
    const float* x     = (const float*)d_in[0];
    const int*   ei    = (const int*)d_in[1];      // int32 [2, E]
    const float* W     = (const float*)d_in[2];
    const float* att_s = (const float*)d_in[3];
    const float* att_d = (const float*)d_in[4];
    const float* bias  = (const float*)d_in[5];
    const float* gamma = (const float*)d_in[6];
    const float* beta  = (const float*)d_in[7];
    float*       out   = (float*)d_out;

    const int gemm_smem = (DIM * WSTR + GM * XSTR) * sizeof(unsigned); // ~134 KB
    cudaFuncSetAttribute(gemm_kernel, cudaFuncAttributeMaxDynamicSharedMemorySize,
                         gemm_smem);

    cudaStream_t side;
    cudaStreamCreateWithFlags(&side, cudaStreamNonBlocking);
    cudaEvent_t eFork, eJoin;
    cudaEventCreateWithFlags(&eFork, cudaEventDisableTiming);
    cudaEventCreateWithFlags(&eJoin, cudaEventDisableTiming);

    cudaEventRecord(eFork, 0);
    cudaStreamWaitEvent(side, eFork, 0);

    // CSR build chain on side stream (no dependence on gemm)
    zero_kernel<<<(NN + 255) / 256, 256, 0, side>>>();
    hist_kernel<<<(EE + 255) / 256, 256, 0, side>>>(ei);
    offsets_kernel<<<(NN + 255) / 256, 256, 0, side>>>();
    scatter_kernel<<<(EE + 255) / 256, 256, 0, side>>>(ei);
    cudaEventRecord(eJoin, side);

    // tf32 mma gemm on main stream, concurrent with CSR build
    gemm_kernel<<<(NN + GM - 1) / GM, 256, gemm_smem>>>(x, W, att_s, att_d);

    cudaStreamWaitEvent(0, eJoin, 0);
    agg_kernel<<<AG_GRID, AG_WARPS * 32>>>(bias);
    final_kernel<<<(NN * 32 + 255) / 256, 256>>>(x, gamma, beta, out);
}

// round 14
// speedup vs baseline: 1.0496x; 1.0496x over previous
#include <cuda_runtime.h>
#include <cuda_fp16.h>

#define NN 100000
#define EE 1600000
#define HH 4
#define CC 32
#define DIM 128
#define NEG_SLOPE 0.2f
#define BN_EPS 1e-5f

// ---------------- scratch (static device globals; no allocs allowed) -------
__device__ __half2 g_h2[(size_t)NN * (DIM / 2)];  // x @ W in fp16 (25.6 MB)
__device__ float   g_acc[(size_t)NN * DIM];       // normalized+biased v (51.2 MB)
__device__ float   g_asrc[NN * HH];
__device__ float   g_adst[NN * HH];
__device__ int     g_deg[NN];
__device__ int     g_off[NN];
__device__ int     g_cur[NN];
__device__ int     g_total;
__device__ int     g_srcs[EE];                    // CSR src ids (6.4 MB)
__device__ float   g_colsum[DIM];
__device__ float   g_colsq[DIM];

// ---------------- 0. zero small scratch ------------------------------------
__global__ void zero_kernel() {
    int i = blockIdx.x * blockDim.x + threadIdx.x;
    if (i < NN) g_deg[i] = 0;
    if (i == 0) g_total = 0;
    if (i < DIM) { g_colsum[i] = 0.f; g_colsq[i] = 0.f; }
}

// ---------------- CSR build: histogram, offsets, scatter --------------------
__global__ void hist_kernel(const int* __restrict__ ei) {
    int e = blockIdx.x * blockDim.x + threadIdx.x;
    if (e < EE) atomicAdd(&g_deg[__ldg(&ei[EE + e])], 1);
}

// warp-aggregated slot allocation: buckets are disjoint but NOT ordered by
// node id — agg only needs disjointness.
__global__ void offsets_kernel() {
    int i = blockIdx.x * blockDim.x + threadIdx.x;
    int lane = threadIdx.x & 31;
    int v = (i < NN) ? g_deg[i] : 0;
    int x = v;
#pragma unroll
    for (int d = 1; d < 32; d <<= 1) {
        int y = __shfl_up_sync(0xffffffffu, x, d);
        if (lane >= d) x += y;
    }
    int total = __shfl_sync(0xffffffffu, x, 31);
    int base = 0;
    if (lane == 31 && total > 0) base = atomicAdd(&g_total, total);
    base = __shfl_sync(0xffffffffu, base, 31);
    if (i < NN) {
        int o = base + x - v;
        g_off[i] = o;
        g_cur[i] = o;
    }
}

__global__ void scatter_kernel(const int* __restrict__ ei) {
    int e = blockIdx.x * blockDim.x + threadIdx.x;
    if (e < EE) {
        int s = __ldg(&ei[e]);
        int d = __ldg(&ei[EE + e]);
        int idx = atomicAdd(&g_cur[d], 1);
        g_srcs[idx] = s;
    }
}

// ---------------- 1. h = x @ W via tf32 mma (tensor pipe) ------------------
#define GM 128                       // nodes per block
#define XSTR 132
#define WSTR 136

__device__ __forceinline__ unsigned f2tf32(float f) {
    unsigned u;
    asm("cvt.rna.tf32.f32 %0, %1;" : "=r"(u) : "f"(f));
    return u;
}
__device__ __forceinline__ float pick4(float a, float b, float c, float d, int t) {
    return t == 0 ? a : (t == 1 ? b : (t == 2 ? c : d));
}

__global__ void gemm_kernel(const float* __restrict__ x,
                            const float* __restrict__ W,
                            const float* __restrict__ att_s,
                            const float* __restrict__ att_d) {
    extern __shared__ unsigned smu[];
    unsigned* ws = smu;                   // 128 * 136 words
    unsigned* xs = smu + DIM * WSTR;      // 128 * 132 words
    const int tid = threadIdx.x;
    const int nb  = blockIdx.x * GM;

    for (int i = tid * 4; i < DIM * DIM; i += 256 * 4) {
        int k = i >> 7, n = i & 127;
        float4 w = *(const float4*)&W[i];
        uint4 u = make_uint4(f2tf32(w.x), f2tf32(w.y), f2tf32(w.z), f2tf32(w.w));
        *(uint4*)&ws[k * WSTR + n] = u;
    }
    for (int i = tid * 4; i < GM * DIM; i += 256 * 4) {
        int r = i >> 7, c = i & 127;
        uint4 u = make_uint4(0u, 0u, 0u, 0u);
        if (nb + r < NN) {
            float4 v = *(const float4*)&x[(size_t)(nb + r) * DIM + c];
            u = make_uint4(f2tf32(v.x), f2tf32(v.y), f2tf32(v.z), f2tf32(v.w));
        }
        *(uint4*)&xs[r * XSTR + c] = u;
    }
    __syncthreads();

    const int warp = tid >> 5, lane = tid & 31;
    const int g = lane >> 2, t = lane & 3;
    const unsigned* xw = xs + (warp * 16) * XSTR;

    float d[16][4];
#pragma unroll
    for (int nt = 0; nt < 16; nt++)
#pragma unroll
        for (int j = 0; j < 4; j++) d[nt][j] = 0.f;

#pragma unroll
    for (int ks = 0; ks < 16; ks++) {
        const int k0 = ks * 8;
        unsigned a0 = xw[g * XSTR + k0 + t];
        unsigned a1 = xw[(g + 8) * XSTR + k0 + t];
        unsigned a2 = xw[g * XSTR + k0 + t + 4];
        unsigned a3 = xw[(g + 8) * XSTR + k0 + t + 4];
#pragma unroll
        for (int nt = 0; nt < 16; nt++) {
            unsigned b0 = ws[(k0 + t) * WSTR + nt * 8 + g];
            unsigned b1 = ws[(k0 + t + 4) * WSTR + nt * 8 + g];
            asm volatile(
                "mma.sync.aligned.m16n8k8.row.col.f32.tf32.tf32.f32 "
                "{%0,%1,%2,%3}, {%4,%5,%6,%7}, {%8,%9}, {%0,%1,%2,%3};"
                : "+f"(d[nt][0]), "+f"(d[nt][1]), "+f"(d[nt][2]), "+f"(d[nt][3])
                : "r"(a0), "r"(a1), "r"(a2), "r"(a3), "r"(b0), "r"(b1));
        }
    }

    const int node0 = nb + warp * 16;
    const int row0 = node0 + g, row1 = node0 + g + 8;

    float ps[2][4], pd[2][4];
#pragma unroll
    for (int r = 0; r < 2; r++)
#pragma unroll
        for (int h = 0; h < 4; h++) { ps[r][h] = 0.f; pd[r][h] = 0.f; }

#pragma unroll
    for (int nt = 0; nt < 16; nt++) {
        const int head = nt >> 2;
        const int cc = ((nt & 3) * 8) + 2 * t;
        float2 as = *(const float2*)&att_s[head * CC + cc];
        float2 ad = *(const float2*)&att_d[head * CC + cc];
        ps[0][head] += d[nt][0] * as.x + d[nt][1] * as.y;
        ps[1][head] += d[nt][2] * as.x + d[nt][3] * as.y;
        pd[0][head] += d[nt][0] * ad.x + d[nt][1] * ad.y;
        pd[1][head] += d[nt][2] * ad.x + d[nt][3] * ad.y;
    }
#pragma unroll
    for (int r = 0; r < 2; r++)
#pragma unroll
        for (int h = 0; h < 4; h++) {
            ps[r][h] += __shfl_xor_sync(0xffffffffu, ps[r][h], 1);
            ps[r][h] += __shfl_xor_sync(0xffffffffu, ps[r][h], 2);
            pd[r][h] += __shfl_xor_sync(0xffffffffu, pd[r][h], 1);
            pd[r][h] += __shfl_xor_sync(0xffffffffu, pd[r][h], 2);
        }
    if (row0 < NN) {
        g_asrc[row0 * HH + t] = pick4(ps[0][0], ps[0][1], ps[0][2], ps[0][3], t);
        g_adst[row0 * HH + t] = pick4(pd[0][0], pd[0][1], pd[0][2], pd[0][3], t);
    }
    if (row1 < NN) {
        g_asrc[row1 * HH + t] = pick4(ps[1][0], ps[1][1], ps[1][2], ps[1][3], t);
        g_adst[row1 * HH + t] = pick4(pd[1][0], pd[1][1], pd[1][2], pd[1][3], t);
    }

#pragma unroll
    for (int nt = 0; nt < 16; nt++) {
        if (row0 < NN)
            g_h2[(size_t)row0 * (DIM / 2) + nt * 4 + t] =
                __floats2half2_rn(d[nt][0], d[nt][1]);
        if (row1 < NN)
            g_h2[(size_t)row1 * (DIM / 2) + nt * 4 + t] =
                __floats2half2_rn(d[nt][2], d[nt][3]);
    }
}

// ---------------- 2. gather-aggregate, one warp per dst (no atomics) -------
// R12 body: single-stage software pipeline — next dst's metadata
// (deg/off/logits/self-row) prefetched during current dst's processing.
#define AG_WARPS 8
#define AG_GRID  592
#define AG_STEP  (AG_GRID * AG_WARPS)
__global__ void agg_kernel(const float* __restrict__ bias) {
    __shared__ float4 s_sum[AG_WARPS * 32];
    __shared__ float4 s_sq [AG_WARPS * 32];
    const int warp = threadIdx.x >> 5, lane = threadIdx.x & 31;
    const int ph = lane & 3;           // head this lane's logit belongs to
    const int pe = lane >> 2;          // edge slot (0..7) this lane scores
    const int myh = lane >> 3;         // head of this lane's 4 columns
    const float4 bv = *(const float4*)&bias[lane * 4];

    float4 csum = make_float4(0.f, 0.f, 0.f, 0.f);
    float4 csq  = make_float4(0.f, 0.f, 0.f, 0.f);

    int dst = blockIdx.x * AG_WARPS + warp;
    // prologue prefetch for first dst
    int deg = 0, off = 0;
    float adp = 0.f, asp = 0.f;
    uint2 rs = make_uint2(0u, 0u);
    if (dst < NN) {
        deg = g_deg[dst]; off = g_off[dst];
        adp = __ldg(&g_adst[dst * HH + ph]);
        asp = __ldg(&g_asrc[dst * HH + ph]);
        rs  = *(const uint2*)&g_h2[(size_t)dst * (DIM / 2) + lane * 2];
    }

    while (dst < NN) {
        // ---- prefetch metadata for next dst (overlaps current processing) --
        const int nd = dst + AG_STEP;
        int ndeg = 0, noff = 0;
        float nadp = 0.f, nasp = 0.f;
        uint2 nrs = make_uint2(0u, 0u);
        if (nd < NN) {
            ndeg = g_deg[nd]; noff = g_off[nd];
            nadp = __ldg(&g_adst[nd * HH + ph]);
            nasp = __ldg(&g_asrc[nd * HH + ph]);
            nrs  = *(const uint2*)&g_h2[(size_t)nd * (DIM / 2) + lane * 2];
        }

        // ---- process current dst -------------------------------------------
        float l0 = asp + adp;
        l0 = l0 > 0.f ? l0 : NEG_SLOPE * l0;
        float p_self = __expf(l0);
        float s_part = (lane < 4) ? p_self : 0.f;

        float pw0 = __shfl_sync(0xffffffffu, p_self, myh);
        float2 a0 = __half22float2(*(__half2*)&rs.x);
        float2 a1 = __half22float2(*(__half2*)&rs.y);
        float4 acc = make_float4(a0.x * pw0, a0.y * pw0, a1.x * pw0, a1.y * pw0);

        for (int c = 0; c < deg; c += 32) {
            const int nc = min(32, deg - c);
            int sv = 0;
            if (lane < nc) sv = __ldg(&g_srcs[off + c + lane]);

#pragma unroll
            for (int h = 0; h < 2; h++) {
                const int e0 = h * 16;
                const int nv = nc - e0;               // valid edges this half
                if (nv <= 0) break;

                float pA = 0.f, pB = 0.f;
                int sA = __shfl_sync(0xffffffffu, sv, e0 + pe);
                int sB = __shfl_sync(0xffffffffu, sv, e0 + pe + 8);
                if (pe < nv) {
                    float ll = __ldg(&g_asrc[sA * HH + ph]) + adp;
                    ll = ll > 0.f ? ll : NEG_SLOPE * ll;
                    pA = __expf(ll);
                }
                if (pe + 8 < nv) {
                    float ll = __ldg(&g_asrc[sB * HH + ph]) + adp;
                    ll = ll > 0.f ? ll : NEG_SLOPE * ll;
                    pB = __expf(ll);
                }
                s_part += pA + pB;

                uint2 raw[16];
#pragma unroll
                for (int e = 0; e < 16; e++) {
                    if (e < nv) {                     // warp-uniform
                        int se = __shfl_sync(0xffffffffu, sv, e0 + e);
                        raw[e] = *(const uint2*)&g_h2[(size_t)se * (DIM / 2) + lane * 2];
                    }
                }
#pragma unroll
                for (int e = 0; e < 16; e++) {
                    if (e < nv) {
                        float pw = (e < 8)
                            ? __shfl_sync(0xffffffffu, pA, e * 4 + myh)
                            : __shfl_sync(0xffffffffu, pB, (e - 8) * 4 + myh);
                        float2 f0 = __half22float2(*(__half2*)&raw[e].x);
                        float2 f1 = __half22float2(*(__half2*)&raw[e].y);
                        acc.x = fmaf(f0.x, pw, acc.x);
                        acc.y = fmaf(f0.y, pw, acc.y);
                        acc.z = fmaf(f1.x, pw, acc.z);
                        acc.w = fmaf(f1.y, pw, acc.w);
                    }
                }
            }
        }

        float st = s_part;
        st += __shfl_xor_sync(0xffffffffu, st, 4);
        st += __shfl_xor_sync(0xffffffffu, st, 8);
        st += __shfl_xor_sync(0xffffffffu, st, 16);
        float r = 1.f / (__shfl_sync(0xffffffffu, st, myh) + 1e-16f);

        float4 v;
        v.x = fmaf(acc.x, r, bv.x);
        v.y = fmaf(acc.y, r, bv.y);
        v.z = fmaf(acc.z, r, bv.z);
        v.w = fmaf(acc.w, r, bv.w);
        *(float4*)&g_acc[(size_t)dst * DIM + lane * 4] = v;

        csum.x += v.x; csum.y += v.y; csum.z += v.z; csum.w += v.w;
        csq.x = fmaf(v.x, v.x, csq.x); csq.y = fmaf(v.y, v.y, csq.y);
        csq.z = fmaf(v.z, v.z, csq.z); csq.w = fmaf(v.w, v.w, csq.w);

        // ---- rotate pipeline ----
        dst = nd; deg = ndeg; off = noff; adp = nadp; asp = nasp; rs = nrs;
    }

    s_sum[warp * 32 + lane] = csum;
    s_sq [warp * 32 + lane] = csq;
    __syncthreads();
    if (warp == 0) {
#pragma unroll
        for (int w = 1; w < AG_WARPS; w++) {
            float4 a = s_sum[w * 32 + lane], b = s_sq[w * 32 + lane];
            csum.x += a.x; csum.y += a.y; csum.z += a.z; csum.w += a.w;
            csq.x  += b.x; csq.y  += b.y; csq.z  += b.z; csq.w  += b.w;
        }
        atomicAdd(&g_colsum[lane * 4 + 0], csum.x);
        atomicAdd(&g_colsum[lane * 4 + 1], csum.y);
        atomicAdd(&g_colsum[lane * 4 + 2], csum.z);
        atomicAdd(&g_colsum[lane * 4 + 3], csum.w);
        atomicAdd(&g_colsq[lane * 4 + 0], csq.x);
        atomicAdd(&g_colsq[lane * 4 + 1], csq.y);
        atomicAdd(&g_colsq[lane * 4 + 2], csq.z);
        atomicAdd(&g_colsq[lane * 4 + 3], csq.w);
    }
}

// ---------------- 3. BN fold + apply + residual + ReLU ---------------------
__global__ void final_kernel(const float* __restrict__ x,
                             const float* __restrict__ gamma,
                             const float* __restrict__ beta,
                             float* __restrict__ out) {
    int i = blockIdx.x * blockDim.x + threadIdx.x;   // float4 index
    if (i >= NN * DIM / 4) return;
    int cb = (i & 31) * 4;
    float4 cs = *(const float4*)&g_colsum[cb];
    float4 cq = *(const float4*)&g_colsq[cb];
    float4 gm = *(const float4*)&gamma[cb];
    float4 bt = *(const float4*)&beta[cb];
    const float invn = 1.f / NN;
    float mx = cs.x * invn, my = cs.y * invn, mz = cs.z * invn, mw = cs.w * invn;
    float scx = gm.x * rsqrtf(cq.x * invn - mx * mx + BN_EPS);
    float scy = gm.y * rsqrtf(cq.y * invn - my * my + BN_EPS);
    float scz = gm.z * rsqrtf(cq.z * invn - mz * mz + BN_EPS);
    float scw = gm.w * rsqrtf(cq.w * invn - mw * mw + BN_EPS);
    float shx = bt.x - mx * scx, shy = bt.y - my * scy;
    float shz = bt.z - mz * scz, shw = bt.w - mw * scw;

    float4 v  = ((const float4*)g_acc)[i];
    float4 xv = ((const float4*)x)[i];
    float4 o;
    o.x = fmaxf(fmaf(scx, v.x, shx) + xv.x, 0.f);
    o.y = fmaxf(fmaf(scy, v.y, shy) + xv.y, 0.f);
    o.z = fmaxf(fmaf(scz, v.z, shz) + xv.z, 0.f);
    o.w = fmaxf(fmaf(scw, v.w, shw) + xv.w, 0.f);
    ((float4*)out)[i] = o;
}

// ---------------- launch ----------------------------------------------------
extern "C" void kernel_launch(void* const* d_in, const int* in_sizes, int n_in,
                              void* d_out, int out_size) {
    const float* x     = (const float*)d_in[0];
    const int*   ei    = (const int*)d_in[1];      // int32 [2, E]
    const float* W     = (const float*)d_in[2];
    const float* att_s = (const float*)d_in[3];
    const float* att_d = (const float*)d_in[4];
    const float* bias  = (const float*)d_in[5];
    const float* gamma = (const float*)d_in[6];
    const float* beta  = (const float*)d_in[7];
    float*       out   = (float*)d_out;

    const int gemm_smem = (DIM * WSTR + GM * XSTR) * sizeof(unsigned); // ~134 KB
    cudaFuncSetAttribute(gemm_kernel, cudaFuncAttributeMaxDynamicSharedMemorySize,
                         gemm_smem);

    cudaStream_t side;
    cudaStreamCreateWithFlags(&side, cudaStreamNonBlocking);
    cudaEvent_t eFork, eJoin;
    cudaEventCreateWithFlags(&eFork, cudaEventDisableTiming);
    cudaEventCreateWithFlags(&eJoin, cudaEventDisableTiming);

    cudaEventRecord(eFork, 0);
    cudaStreamWaitEvent(side, eFork, 0);

    // CSR build chain on side stream (no dependence on gemm)
    zero_kernel<<<(NN + 255) / 256, 256, 0, side>>>();
    hist_kernel<<<(EE + 255) / 256, 256, 0, side>>>(ei);
    offsets_kernel<<<(NN + 255) / 256, 256, 0, side>>>();
    scatter_kernel<<<(EE + 255) / 256, 256, 0, side>>>(ei);
    cudaEventRecord(eJoin, side);

    // tf32 mma gemm on main stream, concurrent with CSR build
    gemm_kernel<<<(NN + GM - 1) / GM, 256, gemm_smem>>>(x, W, att_s, att_d);

    cudaStreamWaitEvent(0, eJoin, 0);
    agg_kernel<<<AG_GRID, AG_WARPS * 32>>>(bias);
    final_kernel<<<(NN * 32 + 255) / 256, 256>>>(x, gamma, beta, out);
}